// round 6
// baseline (speedup 1.0000x reference)
#include <cuda_runtime.h>
#include <cuda_bf16.h>
#include <math.h>

#define BB    128
#define NSEQ  256
#define DD    512          // NODE
#define DEMB_ 256
#define KTOP  8
#define LABELS_ 19

// ---------------- scratch (device globals; no allocations) ----------------
__device__ float    g_x[BB * NSEQ * DD];       // node features [B,N,512]
__device__ float    g_xn[BB * NSEQ * DD];      // y = x@qw
__device__ float    g_adj[BB * NSEQ * NSEQ];   // sim
__device__ float    g_comb[BB * NSEQ * DD];    // gcn_out + conv_out
__device__ float    g_entcat[BB * 2 * DEMB_];
__device__ float    g_rnorm[BB * NSEQ];
__device__ float    g_vals[BB * NSEQ * KTOP];
__device__ int      g_idx[BB * NSEQ * KTOP];
__device__ unsigned g_xh[BB * NSEQ * 256];     // bf16x2 hi, k-pairs packed
__device__ unsigned g_xl[BB * NSEQ * 256];     // bf16x2 lo
__device__ unsigned g_wq[256 * DD];            // quantized W, word[kp*512+n] = (q(2kp,n),q(2kp+1,n))
__device__ int      g_incnt[BB * NSEQ];
__device__ int      g_inm[BB * NSEQ * 256];
__device__ float    g_inv[BB * NSEQ * 256];

// ---------------- bf16 helpers ----------------
__device__ __forceinline__ unsigned pack2(float a, float b) {
    __nv_bfloat162 v = __floats2bfloat162_rn(a, b);
    return *(unsigned*)&v;
}
__device__ __forceinline__ void split2(float x, float& h, float& l) {
    __nv_bfloat16 hb = __float2bfloat16_rn(x);
    h = __bfloat162float(hb);
    l = x - h;
}
__device__ __forceinline__ void mma_bf16(float* d, const unsigned* a, const unsigned* b) {
    asm volatile(
        "mma.sync.aligned.m16n8k16.row.col.f32.bf16.bf16.f32 "
        "{%0,%1,%2,%3}, {%4,%5,%6,%7}, {%8,%9}, {%0,%1,%2,%3};"
        : "+f"(d[0]), "+f"(d[1]), "+f"(d[2]), "+f"(d[3])
        : "r"(a[0]), "r"(a[1]), "r"(a[2]), "r"(a[3]), "r"(b[0]), "r"(b[1]));
}

// ---------------- embedding gather ----------------
__global__ void k_embed(const int* __restrict__ ids, const float* __restrict__ emb) {
    int row = blockIdx.x;
    int id = ids[row];
    const float4* src = (const float4*)(emb + (size_t)id * DEMB_);
    float4* dst = (float4*)(g_x + (size_t)row * DD);
    dst[threadIdx.x] = src[threadIdx.x];
}

// ---------------- entity masked-mean pooling ----------------
__global__ void k_entpool(const float* __restrict__ e1, const float* __restrict__ e2) {
    int b = blockIdx.x;
    int t = threadIdx.x;
    __shared__ float m1[NSEQ], m2[NSEQ];
    __shared__ float c1s, c2s;
    m1[t] = e1[b * NSEQ + t];
    m2[t] = e2[b * NSEQ + t];
    __syncthreads();
    if (t == 0) {
        float a = 0.f, c = 0.f;
        for (int n = 0; n < NSEQ; n++) { a += m1[n]; c += m2[n]; }
        c1s = a; c2s = c;
    }
    __syncthreads();
    float s1 = 0.f, s2 = 0.f;
    const float* xb = g_x + (size_t)b * NSEQ * DD;
    for (int n = 0; n < NSEQ; n++) {
        float v = xb[(size_t)n * DD + t];
        s1 += v * m1[n];
        s2 += v * m2[n];
    }
    g_entcat[b * 512 + t]       = s1 / (c1s + 1e-13f);
    g_entcat[b * 512 + 256 + t] = s2 / (c2s + 1e-13f);
}

// ---------------- ent = entcat @ ep_w + ep_b, broadcast ----------------
__global__ void k_entproj(const float* __restrict__ ep_w, const float* __restrict__ ep_b) {
    int b = blockIdx.x;
    int j = threadIdx.x;
    __shared__ float ec[512];
    __shared__ float accs[256];
    ec[j]       = g_entcat[b * 512 + j];
    ec[j + 256] = g_entcat[b * 512 + j + 256];
    __syncthreads();
    float acc = ep_b[j];
    for (int d = 0; d < 512; d++) acc += ec[d] * ep_w[d * DEMB_ + j];
    accs[j] = acc;
    __syncthreads();
    float* xb = g_x + (size_t)b * NSEQ * DD;
    for (int i = j; i < NSEQ * 256; i += 256) {
        int n = i >> 8, c = i & 255;
        xb[(size_t)n * DD + DEMB_ + c] = accs[c];
    }
}

// ---------------- presplit: x -> bf16x2 hi/lo + inv-norms (fused) ----------------
__global__ void k_presplit() {
    int row = blockIdx.x * 8 + (threadIdx.x >> 5);
    int lane = threadIdx.x & 31;
    const float4* xr = (const float4*)(g_x + (size_t)row * DD);
    uint2* xh2 = (uint2*)(g_xh + (size_t)row * 256);
    uint2* xl2 = (uint2*)(g_xl + (size_t)row * 256);
    float ss = 0.f;
    #pragma unroll
    for (int q = 0; q < 4; q++) {
        int w = lane + q * 32;
        float4 v = xr[w];
        ss += v.x * v.x + v.y * v.y + v.z * v.z + v.w * v.w;
        float hx, lx, hy, ly, hz, lz, hw, lw;
        split2(v.x, hx, lx); split2(v.y, hy, ly);
        split2(v.z, hz, lz); split2(v.w, hw, lw);
        uint2 H; H.x = pack2(hx, hy); H.y = pack2(hz, hw);
        uint2 L; L.x = pack2(lx, ly); L.y = pack2(lz, lw);
        xh2[w] = H;
        xl2[w] = L;
    }
    #pragma unroll
    for (int o = 16; o > 0; o >>= 1) ss += __shfl_xor_sync(0xffffffffu, ss, o);
    if (lane == 0) g_rnorm[row] = 1.f / fmaxf(sqrtf(ss), 1e-12f);
}

// ---------------- quantize W into packed bf16x2 k-pairs ----------------
__global__ void k_wquant(const float* __restrict__ W) {
    int t = blockIdx.x * 256 + threadIdx.x;   // t = kp*512 + n, kp<256
    int kp = t >> 9, n = t & 511;
    float w0 = W[(size_t)(2 * kp) * DD + n];
    float w1 = W[(size_t)(2 * kp + 1) * DD + n];
    float q0 = (w0 > 0.1f) ? 1.f : ((w0 < -0.1f) ? -1.f : 0.f);
    float q1 = (w1 > 0.1f) ? 1.f : ((w1 < -0.1f) ? -1.f : 0.f);
    g_wq[t] = pack2(q0, q1);
}

// ---------------- sim = (x @ x^T) * rn_i * rn_j via 2-split bf16 MMA ----------------
__global__ __launch_bounds__(256) void k_sim_mma() {
    int b = blockIdx.z;
    int i0 = blockIdx.y * 128, j0 = blockIdx.x * 64;
    size_t bN = (size_t)b * NSEQ;
    __shared__ unsigned Ah[8][136], Al[8][136];
    __shared__ unsigned Bh[8][72],  Bl[8][72];
    __shared__ float rnI[128], rnJ[64];
    int t = threadIdx.x;
    int lane = t & 31, wid = t >> 5;
    int wm = wid >> 1, wn = wid & 1;
    int g = lane >> 2, tig = lane & 3;
    if (t < 128) rnI[t] = g_rnorm[bN + i0 + t];
    else if (t < 192) rnJ[t - 128] = g_rnorm[bN + j0 + t - 128];
    float acc[2][4][4];
    #pragma unroll
    for (int a = 0; a < 2; a++)
        #pragma unroll
        for (int n = 0; n < 4; n++)
            #pragma unroll
            for (int e = 0; e < 4; e++) acc[a][n][e] = 0.f;

    int arow = t >> 1, aseg = t & 1;
    for (int kw = 0; kw < 256; kw += 8) {
        {
            uint4 h = *(const uint4*)(g_xh + (bN + i0 + arow) * 256 + kw + aseg * 4);
            uint4 l = *(const uint4*)(g_xl + (bN + i0 + arow) * 256 + kw + aseg * 4);
            Ah[aseg * 4 + 0][arow] = h.x; Ah[aseg * 4 + 1][arow] = h.y;
            Ah[aseg * 4 + 2][arow] = h.z; Ah[aseg * 4 + 3][arow] = h.w;
            Al[aseg * 4 + 0][arow] = l.x; Al[aseg * 4 + 1][arow] = l.y;
            Al[aseg * 4 + 2][arow] = l.z; Al[aseg * 4 + 3][arow] = l.w;
        }
        if (t < 128) {
            int r = t >> 1, s = t & 1;
            uint4 h = *(const uint4*)(g_xh + (bN + j0 + r) * 256 + kw + s * 4);
            Bh[s * 4 + 0][r] = h.x; Bh[s * 4 + 1][r] = h.y;
            Bh[s * 4 + 2][r] = h.z; Bh[s * 4 + 3][r] = h.w;
        } else {
            int tt = t - 128;
            int r = tt >> 1, s = tt & 1;
            uint4 l = *(const uint4*)(g_xl + (bN + j0 + r) * 256 + kw + s * 4);
            Bl[s * 4 + 0][r] = l.x; Bl[s * 4 + 1][r] = l.y;
            Bl[s * 4 + 2][r] = l.z; Bl[s * 4 + 3][r] = l.w;
        }
        __syncthreads();
        unsigned ah[2][4], al[2][4], bh[4][2], bl[4][2];
        #pragma unroll
        for (int mt = 0; mt < 2; mt++) {
            int r = wm * 32 + mt * 16 + g;
            ah[mt][0] = Ah[tig][r];     ah[mt][1] = Ah[tig][r + 8];
            ah[mt][2] = Ah[tig + 4][r]; ah[mt][3] = Ah[tig + 4][r + 8];
            al[mt][0] = Al[tig][r];     al[mt][1] = Al[tig][r + 8];
            al[mt][2] = Al[tig + 4][r]; al[mt][3] = Al[tig + 4][r + 8];
        }
        #pragma unroll
        for (int nt = 0; nt < 4; nt++) {
            int n = wn * 32 + nt * 8 + g;
            bh[nt][0] = Bh[tig][n]; bh[nt][1] = Bh[tig + 4][n];
            bl[nt][0] = Bl[tig][n]; bl[nt][1] = Bl[tig + 4][n];
        }
        #pragma unroll
        for (int mt = 0; mt < 2; mt++)
            #pragma unroll
            for (int nt = 0; nt < 4; nt++) {
                mma_bf16(acc[mt][nt], ah[mt], bh[nt]);
                mma_bf16(acc[mt][nt], ah[mt], bl[nt]);
                mma_bf16(acc[mt][nt], al[mt], bh[nt]);
            }
        __syncthreads();
    }
    float* C = g_adj + (size_t)b * NSEQ * NSEQ;
    #pragma unroll
    for (int mt = 0; mt < 2; mt++)
        #pragma unroll
        for (int nt = 0; nt < 4; nt++) {
            int rl = wm * 32 + mt * 16 + g;
            int cl = wn * 32 + nt * 8 + tig * 2;
            int r = i0 + rl, c = j0 + cl;
            float s0 = rnI[rl] * rnJ[cl], s1 = rnI[rl] * rnJ[cl + 1];
            float s2 = rnI[rl + 8] * rnJ[cl], s3 = rnI[rl + 8] * rnJ[cl + 1];
            C[(size_t)r * NSEQ + c]           = acc[mt][nt][0] * s0;
            C[(size_t)r * NSEQ + c + 1]       = acc[mt][nt][1] * s1;
            C[(size_t)(r + 8) * NSEQ + c]     = acc[mt][nt][2] * s2;
            C[(size_t)(r + 8) * NSEQ + c + 1] = acc[mt][nt][3] * s3;
        }
}

// ---------------- top-8 with coalesced smem staging ----------------
__global__ __launch_bounds__(128) void k_topk() {
    __shared__ float sh[128][36];
    int rb = blockIdx.x * 128;
    int t = threadIdx.x;
    float v[KTOP]; int id[KTOP];
    #pragma unroll
    for (int k = 0; k < KTOP; k++) { v[k] = -1e30f; id[k] = -1; }
    for (int ch = 0; ch < 8; ch++) {
        __syncthreads();
        for (int q = t; q < 1024; q += 128) {
            int row = q >> 3, c4 = q & 7;
            float4 x = *(const float4*)(g_adj + (size_t)(rb + row) * NSEQ + ch * 32 + c4 * 4);
            *(float4*)&sh[row][c4 * 4] = x;
        }
        __syncthreads();
        #pragma unroll 4
        for (int c = 0; c < 32; c++) {
            float x = sh[t][c];
            if (x > v[KTOP - 1]) {
                int m = ch * 32 + c;
                int p = KTOP - 1;
                while (p > 0 && v[p - 1] < x) { v[p] = v[p - 1]; id[p] = id[p - 1]; p--; }
                v[p] = x; id[p] = m;
            }
        }
    }
    int row = rb + t;
    #pragma unroll
    for (int k = 0; k < KTOP; k++) {
        g_vals[row * KTOP + k] = v[k];
        g_idx[row * KTOP + k]  = id[k];
    }
}

// ---------------- zero incoming counts ----------------
__global__ void k_inzero() {
    int i = blockIdx.x * blockDim.x + threadIdx.x;
    if (i < BB * NSEQ) g_incnt[i] = 0;
}

// ---------------- build incoming adjacency lists ----------------
__global__ void k_inbuild() {
    int t = blockIdx.x * blockDim.x + threadIdx.x;
    if (t >= BB * NSEQ * KTOP) return;
    int row = t >> 3;                 // b*256+n (source node)
    int b = row >> 8;
    int n = row & 255;
    int j = g_idx[t];
    float v = g_vals[t];
    int node = b * 256 + j;           // destination node
    int pos = atomicAdd(&g_incnt[node], 1);
    g_inm[((size_t)node << 8) + pos] = n;
    g_inv[((size_t)node << 8) + pos] = v;
}

// ---------------- xqw = x @ sign(W) * 0.1 via 2-split bf16 MMA (prequantized W) ----------------
__global__ __launch_bounds__(256) void k_xqw_mma() {
    int i0 = blockIdx.y * 128, j0 = blockIdx.x * 64;
    __shared__ unsigned Ah[8][136], Al[8][136];
    __shared__ unsigned Bq[8][72];
    int t = threadIdx.x;
    int lane = t & 31, wid = t >> 5;
    int wm = wid >> 1, wn = wid & 1;
    int g = lane >> 2, tig = lane & 3;
    float acc[2][4][4];
    #pragma unroll
    for (int a = 0; a < 2; a++)
        #pragma unroll
        for (int n = 0; n < 4; n++)
            #pragma unroll
            for (int e = 0; e < 4; e++) acc[a][n][e] = 0.f;

    int arow = t >> 1, aseg = t & 1;
    int bkp = t >> 5, bn = (t & 31) * 2;
    for (int kw = 0; kw < 256; kw += 8) {
        {
            uint4 h = *(const uint4*)(g_xh + (size_t)(i0 + arow) * 256 + kw + aseg * 4);
            uint4 l = *(const uint4*)(g_xl + (size_t)(i0 + arow) * 256 + kw + aseg * 4);
            Ah[aseg * 4 + 0][arow] = h.x; Ah[aseg * 4 + 1][arow] = h.y;
            Ah[aseg * 4 + 2][arow] = h.z; Ah[aseg * 4 + 3][arow] = h.w;
            Al[aseg * 4 + 0][arow] = l.x; Al[aseg * 4 + 1][arow] = l.y;
            Al[aseg * 4 + 2][arow] = l.z; Al[aseg * 4 + 3][arow] = l.w;
        }
        {
            uint2 w = *(const uint2*)(g_wq + (size_t)(kw + bkp) * DD + j0 + bn);
            Bq[bkp][bn] = w.x; Bq[bkp][bn + 1] = w.y;
        }
        __syncthreads();
        unsigned ah[2][4], al[2][4], bq[4][2];
        #pragma unroll
        for (int mt = 0; mt < 2; mt++) {
            int r = wm * 32 + mt * 16 + g;
            ah[mt][0] = Ah[tig][r];     ah[mt][1] = Ah[tig][r + 8];
            ah[mt][2] = Ah[tig + 4][r]; ah[mt][3] = Ah[tig + 4][r + 8];
            al[mt][0] = Al[tig][r];     al[mt][1] = Al[tig][r + 8];
            al[mt][2] = Al[tig + 4][r]; al[mt][3] = Al[tig + 4][r + 8];
        }
        #pragma unroll
        for (int nt = 0; nt < 4; nt++) {
            int n = wn * 32 + nt * 8 + g;
            bq[nt][0] = Bq[tig][n]; bq[nt][1] = Bq[tig + 4][n];
        }
        #pragma unroll
        for (int mt = 0; mt < 2; mt++)
            #pragma unroll
            for (int nt = 0; nt < 4; nt++) {
                mma_bf16(acc[mt][nt], ah[mt], bq[nt]);
                mma_bf16(acc[mt][nt], al[mt], bq[nt]);
            }
        __syncthreads();
    }
    #pragma unroll
    for (int mt = 0; mt < 2; mt++)
        #pragma unroll
        for (int nt = 0; nt < 4; nt++) {
            int r = i0 + wm * 32 + mt * 16 + g;
            int c = j0 + wn * 32 + nt * 8 + tig * 2;
            g_xn[(size_t)r * DD + c]           = 0.1f * acc[mt][nt][0];
            g_xn[(size_t)r * DD + c + 1]       = 0.1f * acc[mt][nt][1];
            g_xn[(size_t)(r + 8) * DD + c]     = 0.1f * acc[mt][nt][2];
            g_xn[(size_t)(r + 8) * DD + c + 1] = 0.1f * acc[mt][nt][3];
        }
}

// ---------------- sparse GCN: gcn_out = relu(adj @ y + bias), adj implicit ----------------
__global__ __launch_bounds__(128) void k_gcn_sparse(const float* __restrict__ bias) {
    int b = blockIdx.y, n = blockIdx.x;
    int node = b * 256 + n;
    int t = threadIdx.x;
    __shared__ int   s_src[264];
    __shared__ float s_val[264];
    __shared__ int   s_cnt;
    if (t == 0) s_cnt = g_incnt[node];
    if (t < 8) {
        s_src[t] = g_idx[node * KTOP + t];
        s_val[t] = g_vals[node * KTOP + t];
    }
    __syncthreads();
    int cnt = s_cnt;
    for (int i = t; i < cnt; i += 128) {
        s_src[8 + i] = g_inm[((size_t)node << 8) + i];
        s_val[8 + i] = g_inv[((size_t)node << 8) + i];
    }
    __syncthreads();
    int tot = 8 + cnt;
    const float* Yb = g_xn + (size_t)b * NSEQ * DD;
    float a0 = 0.f, a1 = 0.f, a2 = 0.f, a3 = 0.f;
    for (int e = 0; e < tot; e++) {
        float v = 0.5f * s_val[e];
        const float* yr = Yb + (size_t)s_src[e] * DD;
        a0 += v * yr[t];
        a1 += v * yr[t + 128];
        a2 += v * yr[t + 256];
        a3 += v * yr[t + 384];
    }
    float* C = g_comb + (size_t)node * DD;
    C[t]       = fmaxf(a0 + bias[t], 0.f);
    C[t + 128] = fmaxf(a1 + bias[t + 128], 0.f);
    C[t + 256] = fmaxf(a2 + bias[t + 256], 0.f);
    C[t + 384] = fmaxf(a3 + bias[t + 384], 0.f);
}

// ---------------- fused conv: 32x64 tile, 2-channel chunks, 4x2 register blocking ----------------
__global__ __launch_bounds__(256) void k_conv(const float* __restrict__ c1w, const float* __restrict__ c1b,
                                              const float* __restrict__ bng, const float* __restrict__ bnb,
                                              const float* __restrict__ c2w, const float* __restrict__ c2b) {
    __shared__ float xt[36][69];
    __shared__ float hs[2][36][69];
    __shared__ float w1s[32][9], w2s[32][9], scs[32], tcs[32];
    int b = blockIdx.z;
    int oy0 = blockIdx.y * 32, ox0 = blockIdx.x * 64;
    int t = threadIdx.x;
    if (t < 32) {
        float s = bng[t] * rsqrtf(1.f + 1e-5f);
        scs[t] = s;
        tcs[t] = c1b[t] * s + bnb[t];
    }
    for (int i = t; i < 288; i += 256) {
        w1s[i / 9][i % 9] = c1w[i];
        w2s[i / 9][i % 9] = c2w[i];
    }
    const float* xb = g_x + (size_t)b * NSEQ * DD;
    for (int i = t; i < 36 * 68; i += 256) {
        int r = i / 68, c = i % 68;
        int gy = oy0 - 2 + r, gx = ox0 - 2 + c;
        xt[r][c] = (gy >= 0 && gy < NSEQ && gx >= 0 && gx < DD) ? xb[(size_t)gy * DD + gx] : 0.f;
    }
    __syncthreads();

    int rg = t & 7, cp = t >> 3;
    int oy = rg * 4, ox = cp * 2;
    float acc[4][2] = {};

    for (int chunk = 0; chunk < 16; chunk++) {
        for (int tau = t; tau < 2 * 9 * 33; tau += 256) {
            int g2 = tau % 9;
            int cloc = (tau / 9) & 1;
            int q = tau / 18;
            int cg = chunk * 2 + cloc;
            int ly0 = g2 * 4, lx0 = q * 2;
            float w[9];
            #pragma unroll
            for (int u = 0; u < 9; u++) w[u] = w1s[cg][u];
            float sc = scs[cg], tc = tcs[cg];
            float hb[6][4];
            #pragma unroll
            for (int yy = 0; yy < 6; yy++) {
                int xr = ly0 + yy;
                bool ok = xr < 36;
                #pragma unroll
                for (int xx = 0; xx < 4; xx++)
                    hb[yy][xx] = ok ? xt[xr][lx0 + xx] : 0.f;
            }
            #pragma unroll
            for (int yy = 0; yy < 4; yy++) {
                int ly = ly0 + yy;
                int gy = oy0 - 1 + ly;
                #pragma unroll
                for (int xx = 0; xx < 2; xx++) {
                    int gx = ox0 - 1 + lx0 + xx;
                    float a = 0.f;
                    #pragma unroll
                    for (int dy = 0; dy < 3; dy++)
                        #pragma unroll
                        for (int dx = 0; dx < 3; dx++)
                            a += hb[yy + dy][xx + dx] * w[dy * 3 + dx];
                    float hv = (gy >= 0 && gy < NSEQ && gx >= 0 && gx < DD)
                                   ? fmaxf(a * sc + tc, 0.f) : 0.f;
                    hs[cloc][ly][lx0 + xx] = hv;
                }
            }
        }
        __syncthreads();
        #pragma unroll
        for (int cloc = 0; cloc < 2; cloc++) {
            int cg = chunk * 2 + cloc;
            float w[9];
            #pragma unroll
            for (int u = 0; u < 9; u++) w[u] = w2s[cg][u];
            float hb[6][4];
            #pragma unroll
            for (int yy = 0; yy < 6; yy++)
                #pragma unroll
                for (int xx = 0; xx < 4; xx++)
                    hb[yy][xx] = hs[cloc][oy + yy][ox + xx];
            #pragma unroll
            for (int yy = 0; yy < 4; yy++)
                #pragma unroll
                for (int xx = 0; xx < 2; xx++)
                    #pragma unroll
                    for (int dy = 0; dy < 3; dy++)
                        #pragma unroll
                        for (int dx = 0; dx < 3; dx++)
                            acc[yy][xx] += hb[yy + dy][xx + dx] * w[dy * 3 + dx];
        }
        __syncthreads();
    }
    float bias = c2b[0];
    #pragma unroll
    for (int yy = 0; yy < 4; yy++)
        #pragma unroll
        for (int xx = 0; xx < 2; xx++)
            hs[0][oy + yy][ox + xx] = acc[yy][xx] + bias;
    __syncthreads();
    float* cb = g_comb + (size_t)b * NSEQ * DD;
    for (int i = t; i < 32 * 64; i += 256) {
        int r = i >> 6, c = i & 63;
        cb[(size_t)(oy0 + r) * DD + ox0 + c] += hs[0][r][c];
    }
}

// ---------------- gate + residual mix ----------------
__global__ void k_gate(const float* __restrict__ gw, const float* __restrict__ gb) {
    int row = blockIdx.x;
    int t = threadIdx.x;
    size_t off = (size_t)row * DD;
    float x1 = g_x[off + t],    x2 = g_x[off + t + 256];
    float c1 = g_comb[off + t], c2 = g_comb[off + t + 256];
    float p = x1 * gw[t] + x2 * gw[t + 256] + c1 * gw[512 + t] + c2 * gw[768 + t];
    #pragma unroll
    for (int o = 16; o > 0; o >>= 1) p += __shfl_xor_sync(0xffffffffu, p, o);
    __shared__ float ws[8];
    if ((t & 31) == 0) ws[t >> 5] = p;
    __syncthreads();
    float tot = ws[0] + ws[1] + ws[2] + ws[3] + ws[4] + ws[5] + ws[6] + ws[7];
    float g = 1.f / (1.f + expf(-(tot + gb[0])));
    g_x[off + t]       = g * x1 + (1.f - g) * c1;
    g_x[off + t + 256] = g * x2 + (1.f - g) * c2;
}

// ---------------- mean pool + classifier ----------------
__global__ void k_cls(const float* __restrict__ w1, const float* __restrict__ b1,
                      const float* __restrict__ w2, const float* __restrict__ b2,
                      float* __restrict__ out) {
    int b = blockIdx.x;
    int t = threadIdx.x;
    __shared__ float pooled[512], h1[512];
    float s = 0.f;
    const float* xb = g_x + (size_t)b * NSEQ * DD;
    for (int n = 0; n < NSEQ; n++) s += xb[(size_t)n * DD + t];
    pooled[t] = s * (1.f / NSEQ);
    __syncthreads();
    float a = b1[t];
    for (int d = 0; d < 512; d++) a += pooled[d] * w1[d * 512 + t];
    h1[t] = fmaxf(a, 0.f);
    __syncthreads();
    if (t < LABELS_) {
        float a2 = b2[t];
        for (int d = 0; d < 512; d++) a2 += h1[d] * w2[d * LABELS_ + t];
        out[b * LABELS_ + t] = a2;
    }
}

// ---------------- launch ----------------
extern "C" void kernel_launch(void* const* d_in, const int* in_sizes, int n_in,
                              void* d_out, int out_size) {
    const int*   ids   = (const int*)  d_in[0];
    const float* e1    = (const float*)d_in[1];
    const float* e2    = (const float*)d_in[2];
    const float* emb   = (const float*)d_in[3];
    const float* ep_w  = (const float*)d_in[4];
    const float* ep_b  = (const float*)d_in[5];
    const float* gcn_w = (const float*)d_in[6];
    const float* gcn_b = (const float*)d_in[7];
    const float* c1w   = (const float*)d_in[8];
    const float* c1b   = (const float*)d_in[9];
    const float* bng   = (const float*)d_in[10];
    const float* bnb   = (const float*)d_in[11];
    const float* c2w   = (const float*)d_in[12];
    const float* c2b   = (const float*)d_in[13];
    const float* gw    = (const float*)d_in[14];
    const float* gb    = (const float*)d_in[15];
    const float* clw1  = (const float*)d_in[16];
    const float* clb1  = (const float*)d_in[17];
    const float* clw2  = (const float*)d_in[18];
    const float* clb2  = (const float*)d_in[19];
    float* out = (float*)d_out;

    k_embed<<<BB * NSEQ, 64>>>(ids, emb);
    k_entpool<<<BB, 256>>>(e1, e2);
    k_entproj<<<BB, 256>>>(ep_w, ep_b);

    for (int i = 0; i < 2; i++) {
        k_presplit<<<BB * NSEQ / 8, 256>>>();
        k_wquant<<<256 * DD / 256, 256>>>(gcn_w + (size_t)i * DD * DD);
        k_sim_mma<<<dim3(4, 2, BB), 256>>>();
        k_topk<<<BB * NSEQ / 128, 128>>>();
        k_inzero<<<BB * NSEQ / 256, 256>>>();
        k_inbuild<<<BB * NSEQ * KTOP / 256, 256>>>();
        k_xqw_mma<<<dim3(8, 256), 256>>>();
        k_gcn_sparse<<<dim3(NSEQ, BB), 128>>>(gcn_b + i * DD);
        k_conv<<<dim3(8, 8, BB), 256>>>(c1w + i * 288, c1b + i * 32,
                                        bng + i * 32, bnb + i * 32,
                                        c2w + i * 288, c2b + i);
        k_gate<<<BB * NSEQ, 256>>>(gw, gb);
    }
    k_cls<<<BB, 512>>>(clw1, clb1, clw2, clb2, out);
}

// round 7
// speedup vs baseline: 1.0102x; 1.0102x over previous
#include <cuda_runtime.h>
#include <cuda_bf16.h>
#include <math.h>

#define BB    128
#define NSEQ  256
#define DD    512          // NODE
#define DEMB_ 256
#define KTOP  8
#define LABELS_ 19

// ---------------- scratch (device globals; no allocations) ----------------
__device__ float    g_x[BB * NSEQ * DD];       // node features [B,N,512]
__device__ float    g_xn[BB * NSEQ * DD];      // y = x@qw
__device__ float    g_adj[BB * NSEQ * NSEQ];   // sim
__device__ float    g_comb[BB * NSEQ * DD];    // gcn_out
__device__ float    g_conv[BB * NSEQ * DD];    // conv branch output (separate for overlap)
__device__ float    g_entcat[BB * 2 * DEMB_];
__device__ float    g_rnorm[BB * NSEQ];
__device__ float    g_vals[BB * NSEQ * KTOP];
__device__ int      g_idx[BB * NSEQ * KTOP];
__device__ unsigned g_xh[BB * NSEQ * 256];     // bf16x2 hi, k-pairs packed
__device__ unsigned g_xl[BB * NSEQ * 256];     // bf16x2 lo
__device__ unsigned g_wq[256 * DD];            // quantized W k-pairs
__device__ int      g_incnt[BB * NSEQ];
__device__ int      g_inm[BB * NSEQ * 256];
__device__ float    g_inv[BB * NSEQ * 256];

// ---------------- bf16 helpers ----------------
__device__ __forceinline__ unsigned pack2(float a, float b) {
    __nv_bfloat162 v = __floats2bfloat162_rn(a, b);
    return *(unsigned*)&v;
}
__device__ __forceinline__ void split2(float x, float& h, float& l) {
    __nv_bfloat16 hb = __float2bfloat16_rn(x);
    h = __bfloat162float(hb);
    l = x - h;
}
__device__ __forceinline__ void mma_bf16(float* d, const unsigned* a, const unsigned* b) {
    asm volatile(
        "mma.sync.aligned.m16n8k16.row.col.f32.bf16.bf16.f32 "
        "{%0,%1,%2,%3}, {%4,%5,%6,%7}, {%8,%9}, {%0,%1,%2,%3};"
        : "+f"(d[0]), "+f"(d[1]), "+f"(d[2]), "+f"(d[3])
        : "r"(a[0]), "r"(a[1]), "r"(a[2]), "r"(a[3]), "r"(b[0]), "r"(b[1]));
}

// ---------------- embedding gather ----------------
__global__ void k_embed(const int* __restrict__ ids, const float* __restrict__ emb) {
    int row = blockIdx.x;
    int id = ids[row];
    const float4* src = (const float4*)(emb + (size_t)id * DEMB_);
    float4* dst = (float4*)(g_x + (size_t)row * DD);
    dst[threadIdx.x] = src[threadIdx.x];
}

// ---------------- entity masked-mean pooling ----------------
__global__ void k_entpool(const float* __restrict__ e1, const float* __restrict__ e2) {
    int b = blockIdx.x;
    int t = threadIdx.x;
    __shared__ float m1[NSEQ], m2[NSEQ];
    __shared__ float c1s, c2s;
    m1[t] = e1[b * NSEQ + t];
    m2[t] = e2[b * NSEQ + t];
    __syncthreads();
    if (t == 0) {
        float a = 0.f, c = 0.f;
        for (int n = 0; n < NSEQ; n++) { a += m1[n]; c += m2[n]; }
        c1s = a; c2s = c;
    }
    __syncthreads();
    float s1 = 0.f, s2 = 0.f;
    const float* xb = g_x + (size_t)b * NSEQ * DD;
    for (int n = 0; n < NSEQ; n++) {
        float v = xb[(size_t)n * DD + t];
        s1 += v * m1[n];
        s2 += v * m2[n];
    }
    g_entcat[b * 512 + t]       = s1 / (c1s + 1e-13f);
    g_entcat[b * 512 + 256 + t] = s2 / (c2s + 1e-13f);
}

// ---------------- ent = entcat @ ep_w + ep_b, broadcast ----------------
__global__ void k_entproj(const float* __restrict__ ep_w, const float* __restrict__ ep_b) {
    int b = blockIdx.x;
    int j = threadIdx.x;
    __shared__ float ec[512];
    __shared__ float accs[256];
    ec[j]       = g_entcat[b * 512 + j];
    ec[j + 256] = g_entcat[b * 512 + j + 256];
    __syncthreads();
    float acc = ep_b[j];
    for (int d = 0; d < 512; d++) acc += ec[d] * ep_w[d * DEMB_ + j];
    accs[j] = acc;
    __syncthreads();
    float* xb = g_x + (size_t)b * NSEQ * DD;
    for (int i = j; i < NSEQ * 256; i += 256) {
        int n = i >> 8, c = i & 255;
        xb[(size_t)n * DD + DEMB_ + c] = accs[c];
    }
}

// ---------------- presplit: x -> bf16x2 hi/lo + inv-norms (layer 0 only) ----------------
__global__ void k_presplit() {
    int row = blockIdx.x * 8 + (threadIdx.x >> 5);
    int lane = threadIdx.x & 31;
    const float4* xr = (const float4*)(g_x + (size_t)row * DD);
    uint2* xh2 = (uint2*)(g_xh + (size_t)row * 256);
    uint2* xl2 = (uint2*)(g_xl + (size_t)row * 256);
    float ss = 0.f;
    #pragma unroll
    for (int q = 0; q < 4; q++) {
        int w = lane + q * 32;
        float4 v = xr[w];
        ss += v.x * v.x + v.y * v.y + v.z * v.z + v.w * v.w;
        float hx, lx, hy, ly, hz, lz, hw, lw;
        split2(v.x, hx, lx); split2(v.y, hy, ly);
        split2(v.z, hz, lz); split2(v.w, hw, lw);
        uint2 H; H.x = pack2(hx, hy); H.y = pack2(hz, hw);
        uint2 L; L.x = pack2(lx, ly); L.y = pack2(lz, lw);
        xh2[w] = H;
        xl2[w] = L;
    }
    #pragma unroll
    for (int o = 16; o > 0; o >>= 1) ss += __shfl_xor_sync(0xffffffffu, ss, o);
    if (lane == 0) g_rnorm[row] = 1.f / fmaxf(sqrtf(ss), 1e-12f);
}

// ---------------- quantize W into packed bf16x2 k-pairs ----------------
__global__ void k_wquant(const float* __restrict__ W) {
    int t = blockIdx.x * 256 + threadIdx.x;
    int kp = t >> 9, n = t & 511;
    float w0 = W[(size_t)(2 * kp) * DD + n];
    float w1 = W[(size_t)(2 * kp + 1) * DD + n];
    float q0 = (w0 > 0.1f) ? 1.f : ((w0 < -0.1f) ? -1.f : 0.f);
    float q1 = (w1 > 0.1f) ? 1.f : ((w1 < -0.1f) ? -1.f : 0.f);
    g_wq[t] = pack2(q0, q1);
}

// ---------------- sim = (x @ x^T) * rn_i * rn_j via 2-split bf16 MMA ----------------
__global__ __launch_bounds__(256) void k_sim_mma() {
    int b = blockIdx.z;
    int i0 = blockIdx.y * 128, j0 = blockIdx.x * 64;
    size_t bN = (size_t)b * NSEQ;
    __shared__ unsigned Ah[8][136], Al[8][136];
    __shared__ unsigned Bh[8][72],  Bl[8][72];
    __shared__ float rnI[128], rnJ[64];
    int t = threadIdx.x;
    int lane = t & 31, wid = t >> 5;
    int wm = wid >> 1, wn = wid & 1;
    int g = lane >> 2, tig = lane & 3;
    if (t < 128) rnI[t] = g_rnorm[bN + i0 + t];
    else if (t < 192) rnJ[t - 128] = g_rnorm[bN + j0 + t - 128];
    float acc[2][4][4];
    #pragma unroll
    for (int a = 0; a < 2; a++)
        #pragma unroll
        for (int n = 0; n < 4; n++)
            #pragma unroll
            for (int e = 0; e < 4; e++) acc[a][n][e] = 0.f;

    int arow = t >> 1, aseg = t & 1;
    for (int kw = 0; kw < 256; kw += 8) {
        {
            uint4 h = *(const uint4*)(g_xh + (bN + i0 + arow) * 256 + kw + aseg * 4);
            uint4 l = *(const uint4*)(g_xl + (bN + i0 + arow) * 256 + kw + aseg * 4);
            Ah[aseg * 4 + 0][arow] = h.x; Ah[aseg * 4 + 1][arow] = h.y;
            Ah[aseg * 4 + 2][arow] = h.z; Ah[aseg * 4 + 3][arow] = h.w;
            Al[aseg * 4 + 0][arow] = l.x; Al[aseg * 4 + 1][arow] = l.y;
            Al[aseg * 4 + 2][arow] = l.z; Al[aseg * 4 + 3][arow] = l.w;
        }
        if (t < 128) {
            int r = t >> 1, s = t & 1;
            uint4 h = *(const uint4*)(g_xh + (bN + j0 + r) * 256 + kw + s * 4);
            Bh[s * 4 + 0][r] = h.x; Bh[s * 4 + 1][r] = h.y;
            Bh[s * 4 + 2][r] = h.z; Bh[s * 4 + 3][r] = h.w;
        } else {
            int tt = t - 128;
            int r = tt >> 1, s = tt & 1;
            uint4 l = *(const uint4*)(g_xl + (bN + j0 + r) * 256 + kw + s * 4);
            Bl[s * 4 + 0][r] = l.x; Bl[s * 4 + 1][r] = l.y;
            Bl[s * 4 + 2][r] = l.z; Bl[s * 4 + 3][r] = l.w;
        }
        __syncthreads();
        unsigned ah[2][4], al[2][4], bh[4][2], bl[4][2];
        #pragma unroll
        for (int mt = 0; mt < 2; mt++) {
            int r = wm * 32 + mt * 16 + g;
            ah[mt][0] = Ah[tig][r];     ah[mt][1] = Ah[tig][r + 8];
            ah[mt][2] = Ah[tig + 4][r]; ah[mt][3] = Ah[tig + 4][r + 8];
            al[mt][0] = Al[tig][r];     al[mt][1] = Al[tig][r + 8];
            al[mt][2] = Al[tig + 4][r]; al[mt][3] = Al[tig + 4][r + 8];
        }
        #pragma unroll
        for (int nt = 0; nt < 4; nt++) {
            int n = wn * 32 + nt * 8 + g;
            bh[nt][0] = Bh[tig][n]; bh[nt][1] = Bh[tig + 4][n];
            bl[nt][0] = Bl[tig][n]; bl[nt][1] = Bl[tig + 4][n];
        }
        #pragma unroll
        for (int mt = 0; mt < 2; mt++)
            #pragma unroll
            for (int nt = 0; nt < 4; nt++) {
                mma_bf16(acc[mt][nt], ah[mt], bh[nt]);
                mma_bf16(acc[mt][nt], ah[mt], bl[nt]);
                mma_bf16(acc[mt][nt], al[mt], bh[nt]);
            }
        __syncthreads();
    }
    float* C = g_adj + (size_t)b * NSEQ * NSEQ;
    #pragma unroll
    for (int mt = 0; mt < 2; mt++)
        #pragma unroll
        for (int nt = 0; nt < 4; nt++) {
            int rl = wm * 32 + mt * 16 + g;
            int cl = wn * 32 + nt * 8 + tig * 2;
            int r = i0 + rl, c = j0 + cl;
            float s0 = rnI[rl] * rnJ[cl], s1 = rnI[rl] * rnJ[cl + 1];
            float s2 = rnI[rl + 8] * rnJ[cl], s3 = rnI[rl + 8] * rnJ[cl + 1];
            C[(size_t)r * NSEQ + c]           = acc[mt][nt][0] * s0;
            C[(size_t)r * NSEQ + c + 1]       = acc[mt][nt][1] * s1;
            C[(size_t)(r + 8) * NSEQ + c]     = acc[mt][nt][2] * s2;
            C[(size_t)(r + 8) * NSEQ + c + 1] = acc[mt][nt][3] * s3;
        }
}

// ---------------- top-8 with coalesced smem staging ----------------
__global__ __launch_bounds__(128) void k_topk() {
    __shared__ float sh[128][36];
    int rb = blockIdx.x * 128;
    int t = threadIdx.x;
    float v[KTOP]; int id[KTOP];
    #pragma unroll
    for (int k = 0; k < KTOP; k++) { v[k] = -1e30f; id[k] = -1; }
    for (int ch = 0; ch < 8; ch++) {
        __syncthreads();
        for (int q = t; q < 1024; q += 128) {
            int row = q >> 3, c4 = q & 7;
            float4 x = *(const float4*)(g_adj + (size_t)(rb + row) * NSEQ + ch * 32 + c4 * 4);
            *(float4*)&sh[row][c4 * 4] = x;
        }
        __syncthreads();
        #pragma unroll 4
        for (int c = 0; c < 32; c++) {
            float x = sh[t][c];
            if (x > v[KTOP - 1]) {
                int m = ch * 32 + c;
                int p = KTOP - 1;
                while (p > 0 && v[p - 1] < x) { v[p] = v[p - 1]; id[p] = id[p - 1]; p--; }
                v[p] = x; id[p] = m;
            }
        }
    }
    int row = rb + t;
    #pragma unroll
    for (int k = 0; k < KTOP; k++) {
        g_vals[row * KTOP + k] = v[k];
        g_idx[row * KTOP + k]  = id[k];
    }
}

// ---------------- zero incoming counts ----------------
__global__ void k_inzero() {
    int i = blockIdx.x * blockDim.x + threadIdx.x;
    if (i < BB * NSEQ) g_incnt[i] = 0;
}

// ---------------- build incoming adjacency lists ----------------
__global__ void k_inbuild() {
    int t = blockIdx.x * blockDim.x + threadIdx.x;
    if (t >= BB * NSEQ * KTOP) return;
    int row = t >> 3;
    int b = row >> 8;
    int n = row & 255;
    int j = g_idx[t];
    float v = g_vals[t];
    int node = b * 256 + j;
    int pos = atomicAdd(&g_incnt[node], 1);
    g_inm[((size_t)node << 8) + pos] = n;
    g_inv[((size_t)node << 8) + pos] = v;
}

// ---------------- xqw = x @ sign(W) * 0.1 via 2-split bf16 MMA ----------------
__global__ __launch_bounds__(256) void k_xqw_mma() {
    int i0 = blockIdx.y * 128, j0 = blockIdx.x * 64;
    __shared__ unsigned Ah[8][136], Al[8][136];
    __shared__ unsigned Bq[8][72];
    int t = threadIdx.x;
    int lane = t & 31, wid = t >> 5;
    int wm = wid >> 1, wn = wid & 1;
    int g = lane >> 2, tig = lane & 3;
    float acc[2][4][4];
    #pragma unroll
    for (int a = 0; a < 2; a++)
        #pragma unroll
        for (int n = 0; n < 4; n++)
            #pragma unroll
            for (int e = 0; e < 4; e++) acc[a][n][e] = 0.f;

    int arow = t >> 1, aseg = t & 1;
    int bkp = t >> 5, bn = (t & 31) * 2;
    for (int kw = 0; kw < 256; kw += 8) {
        {
            uint4 h = *(const uint4*)(g_xh + (size_t)(i0 + arow) * 256 + kw + aseg * 4);
            uint4 l = *(const uint4*)(g_xl + (size_t)(i0 + arow) * 256 + kw + aseg * 4);
            Ah[aseg * 4 + 0][arow] = h.x; Ah[aseg * 4 + 1][arow] = h.y;
            Ah[aseg * 4 + 2][arow] = h.z; Ah[aseg * 4 + 3][arow] = h.w;
            Al[aseg * 4 + 0][arow] = l.x; Al[aseg * 4 + 1][arow] = l.y;
            Al[aseg * 4 + 2][arow] = l.z; Al[aseg * 4 + 3][arow] = l.w;
        }
        {
            uint2 w = *(const uint2*)(g_wq + (size_t)(kw + bkp) * DD + j0 + bn);
            Bq[bkp][bn] = w.x; Bq[bkp][bn + 1] = w.y;
        }
        __syncthreads();
        unsigned ah[2][4], al[2][4], bq[4][2];
        #pragma unroll
        for (int mt = 0; mt < 2; mt++) {
            int r = wm * 32 + mt * 16 + g;
            ah[mt][0] = Ah[tig][r];     ah[mt][1] = Ah[tig][r + 8];
            ah[mt][2] = Ah[tig + 4][r]; ah[mt][3] = Ah[tig + 4][r + 8];
            al[mt][0] = Al[tig][r];     al[mt][1] = Al[tig][r + 8];
            al[mt][2] = Al[tig + 4][r]; al[mt][3] = Al[tig + 4][r + 8];
        }
        #pragma unroll
        for (int nt = 0; nt < 4; nt++) {
            int n = wn * 32 + nt * 8 + g;
            bq[nt][0] = Bq[tig][n]; bq[nt][1] = Bq[tig + 4][n];
        }
        #pragma unroll
        for (int mt = 0; mt < 2; mt++)
            #pragma unroll
            for (int nt = 0; nt < 4; nt++) {
                mma_bf16(acc[mt][nt], ah[mt], bq[nt]);
                mma_bf16(acc[mt][nt], al[mt], bq[nt]);
            }
        __syncthreads();
    }
    #pragma unroll
    for (int mt = 0; mt < 2; mt++)
        #pragma unroll
        for (int nt = 0; nt < 4; nt++) {
            int r = i0 + wm * 32 + mt * 16 + g;
            int c = j0 + wn * 32 + nt * 8 + tig * 2;
            g_xn[(size_t)r * DD + c]           = 0.1f * acc[mt][nt][0];
            g_xn[(size_t)r * DD + c + 1]       = 0.1f * acc[mt][nt][1];
            g_xn[(size_t)(r + 8) * DD + c]     = 0.1f * acc[mt][nt][2];
            g_xn[(size_t)(r + 8) * DD + c + 1] = 0.1f * acc[mt][nt][3];
        }
}

// ---------------- sparse GCN: gcn_out = relu(adj @ y + bias), adj implicit ----------------
__global__ __launch_bounds__(128) void k_gcn_sparse(const float* __restrict__ bias) {
    int b = blockIdx.y, n = blockIdx.x;
    int node = b * 256 + n;
    int t = threadIdx.x;
    __shared__ int   s_src[264];
    __shared__ float s_val[264];
    __shared__ int   s_cnt;
    if (t == 0) s_cnt = g_incnt[node];
    if (t < 8) {
        s_src[t] = g_idx[node * KTOP + t];
        s_val[t] = g_vals[node * KTOP + t];
    }
    __syncthreads();
    int cnt = s_cnt;
    for (int i = t; i < cnt; i += 128) {
        s_src[8 + i] = g_inm[((size_t)node << 8) + i];
        s_val[8 + i] = g_inv[((size_t)node << 8) + i];
    }
    __syncthreads();
    int tot = 8 + cnt;
    const float* Yb = g_xn + (size_t)b * NSEQ * DD;
    float a0 = 0.f, a1 = 0.f, a2 = 0.f, a3 = 0.f;
    for (int e = 0; e < tot; e++) {
        float v = 0.5f * s_val[e];
        const float* yr = Yb + (size_t)s_src[e] * DD;
        a0 += v * yr[t];
        a1 += v * yr[t + 128];
        a2 += v * yr[t + 256];
        a3 += v * yr[t + 384];
    }
    float* C = g_comb + (size_t)node * DD;
    C[t]       = fmaxf(a0 + bias[t], 0.f);
    C[t + 128] = fmaxf(a1 + bias[t + 128], 0.f);
    C[t + 256] = fmaxf(a2 + bias[t + 256], 0.f);
    C[t + 384] = fmaxf(a3 + bias[t + 384], 0.f);
}

// ---------------- fused conv (independent branch; writes g_conv) ----------------
__global__ __launch_bounds__(256) void k_conv(const float* __restrict__ c1w, const float* __restrict__ c1b,
                                              const float* __restrict__ bng, const float* __restrict__ bnb,
                                              const float* __restrict__ c2w, const float* __restrict__ c2b) {
    __shared__ float xt[36][69];
    __shared__ float hs[2][36][69];
    __shared__ float w1s[32][9], w2s[32][9], scs[32], tcs[32];
    int b = blockIdx.z;
    int oy0 = blockIdx.y * 32, ox0 = blockIdx.x * 64;
    int t = threadIdx.x;
    if (t < 32) {
        float s = bng[t] * rsqrtf(1.f + 1e-5f);
        scs[t] = s;
        tcs[t] = c1b[t] * s + bnb[t];
    }
    for (int i = t; i < 288; i += 256) {
        w1s[i / 9][i % 9] = c1w[i];
        w2s[i / 9][i % 9] = c2w[i];
    }
    const float* xb = g_x + (size_t)b * NSEQ * DD;
    for (int i = t; i < 36 * 68; i += 256) {
        int r = i / 68, c = i % 68;
        int gy = oy0 - 2 + r, gx = ox0 - 2 + c;
        xt[r][c] = (gy >= 0 && gy < NSEQ && gx >= 0 && gx < DD) ? xb[(size_t)gy * DD + gx] : 0.f;
    }
    __syncthreads();

    int rg = t & 7, cp = t >> 3;
    int oy = rg * 4, ox = cp * 2;
    float acc[4][2] = {};

    for (int chunk = 0; chunk < 16; chunk++) {
        for (int tau = t; tau < 2 * 9 * 33; tau += 256) {
            int g2 = tau % 9;
            int cloc = (tau / 9) & 1;
            int q = tau / 18;
            int cg = chunk * 2 + cloc;
            int ly0 = g2 * 4, lx0 = q * 2;
            float w[9];
            #pragma unroll
            for (int u = 0; u < 9; u++) w[u] = w1s[cg][u];
            float sc = scs[cg], tc = tcs[cg];
            float hb[6][4];
            #pragma unroll
            for (int yy = 0; yy < 6; yy++) {
                int xr = ly0 + yy;
                bool ok = xr < 36;
                #pragma unroll
                for (int xx = 0; xx < 4; xx++)
                    hb[yy][xx] = ok ? xt[xr][lx0 + xx] : 0.f;
            }
            #pragma unroll
            for (int yy = 0; yy < 4; yy++) {
                int ly = ly0 + yy;
                int gy = oy0 - 1 + ly;
                #pragma unroll
                for (int xx = 0; xx < 2; xx++) {
                    int gx = ox0 - 1 + lx0 + xx;
                    float a = 0.f;
                    #pragma unroll
                    for (int dy = 0; dy < 3; dy++)
                        #pragma unroll
                        for (int dx = 0; dx < 3; dx++)
                            a += hb[yy + dy][xx + dx] * w[dy * 3 + dx];
                    float hv = (gy >= 0 && gy < NSEQ && gx >= 0 && gx < DD)
                                   ? fmaxf(a * sc + tc, 0.f) : 0.f;
                    hs[cloc][ly][lx0 + xx] = hv;
                }
            }
        }
        __syncthreads();
        #pragma unroll
        for (int cloc = 0; cloc < 2; cloc++) {
            int cg = chunk * 2 + cloc;
            float w[9];
            #pragma unroll
            for (int u = 0; u < 9; u++) w[u] = w2s[cg][u];
            float hb[6][4];
            #pragma unroll
            for (int yy = 0; yy < 6; yy++)
                #pragma unroll
                for (int xx = 0; xx < 4; xx++)
                    hb[yy][xx] = hs[cloc][oy + yy][ox + xx];
            #pragma unroll
            for (int yy = 0; yy < 4; yy++)
                #pragma unroll
                for (int xx = 0; xx < 2; xx++)
                    #pragma unroll
                    for (int dy = 0; dy < 3; dy++)
                        #pragma unroll
                        for (int dx = 0; dx < 3; dx++)
                            acc[yy][xx] += hb[yy + dy][xx + dx] * w[dy * 3 + dx];
        }
        __syncthreads();
    }
    float bias = c2b[0];
    #pragma unroll
    for (int yy = 0; yy < 4; yy++)
        #pragma unroll
        for (int xx = 0; xx < 2; xx++)
            hs[0][oy + yy][ox + xx] = acc[yy][xx] + bias;
    __syncthreads();
    float* cb = g_conv + (size_t)b * NSEQ * DD;
    for (int i = t; i < 32 * 64; i += 256) {
        int r = i >> 6, c = i & 63;
        cb[(size_t)(oy0 + r) * DD + ox0 + c] = hs[0][r][c];
    }
}

// ---------------- gate + residual mix (+ optional split/norm emit for next layer) ----------------
__global__ void k_gate(const float* __restrict__ gw, const float* __restrict__ gb, int emit) {
    int row = blockIdx.x;
    int t = threadIdx.x;
    size_t off = (size_t)row * DD;
    __shared__ float ws[8], ws2[8];
    __shared__ float xr[512];
    float x1 = g_x[off + t],    x2 = g_x[off + t + 256];
    float c1 = g_comb[off + t] + g_conv[off + t];
    float c2 = g_comb[off + t + 256] + g_conv[off + t + 256];
    float p = x1 * gw[t] + x2 * gw[t + 256] + c1 * gw[512 + t] + c2 * gw[768 + t];
    #pragma unroll
    for (int o = 16; o > 0; o >>= 1) p += __shfl_xor_sync(0xffffffffu, p, o);
    if ((t & 31) == 0) ws[t >> 5] = p;
    __syncthreads();
    float tot = ws[0] + ws[1] + ws[2] + ws[3] + ws[4] + ws[5] + ws[6] + ws[7];
    float g = 1.f / (1.f + expf(-(tot + gb[0])));
    float y1 = g * x1 + (1.f - g) * c1;
    float y2 = g * x2 + (1.f - g) * c2;
    g_x[off + t]       = y1;
    g_x[off + t + 256] = y2;
    if (emit) {
        xr[t] = y1; xr[t + 256] = y2;
        float ssp = y1 * y1 + y2 * y2;
        #pragma unroll
        for (int o = 16; o > 0; o >>= 1) ssp += __shfl_xor_sync(0xffffffffu, ssp, o);
        if ((t & 31) == 0) ws2[t >> 5] = ssp;
        __syncthreads();
        if (t == 0) {
            float ss = ws2[0] + ws2[1] + ws2[2] + ws2[3] + ws2[4] + ws2[5] + ws2[6] + ws2[7];
            g_rnorm[row] = 1.f / fmaxf(sqrtf(ss), 1e-12f);
        }
        float a = xr[2 * t], bb = xr[2 * t + 1];
        float ha, la, hb2, lb2;
        split2(a, ha, la);
        split2(bb, hb2, lb2);
        g_xh[(size_t)row * 256 + t] = pack2(ha, hb2);
        g_xl[(size_t)row * 256 + t] = pack2(la, lb2);
    }
}

// ---------------- mean pool + classifier ----------------
__global__ void k_cls(const float* __restrict__ w1, const float* __restrict__ b1,
                      const float* __restrict__ w2, const float* __restrict__ b2,
                      float* __restrict__ out) {
    int b = blockIdx.x;
    int t = threadIdx.x;
    __shared__ float pooled[512], h1[512];
    float s = 0.f;
    const float* xb = g_x + (size_t)b * NSEQ * DD;
    for (int n = 0; n < NSEQ; n++) s += xb[(size_t)n * DD + t];
    pooled[t] = s * (1.f / NSEQ);
    __syncthreads();
    float a = b1[t];
    for (int d = 0; d < 512; d++) a += pooled[d] * w1[d * 512 + t];
    h1[t] = fmaxf(a, 0.f);
    __syncthreads();
    if (t < LABELS_) {
        float a2 = b2[t];
        for (int d = 0; d < 512; d++) a2 += h1[d] * w2[d * LABELS_ + t];
        out[b * LABELS_ + t] = a2;
    }
}

// ---------------- launch ----------------
static cudaStream_t g_s1 = nullptr;
static cudaEvent_t  g_eF[2], g_eC[2];

extern "C" void kernel_launch(void* const* d_in, const int* in_sizes, int n_in,
                              void* d_out, int out_size) {
    const int*   ids   = (const int*)  d_in[0];
    const float* e1    = (const float*)d_in[1];
    const float* e2    = (const float*)d_in[2];
    const float* emb   = (const float*)d_in[3];
    const float* ep_w  = (const float*)d_in[4];
    const float* ep_b  = (const float*)d_in[5];
    const float* gcn_w = (const float*)d_in[6];
    const float* gcn_b = (const float*)d_in[7];
    const float* c1w   = (const float*)d_in[8];
    const float* c1b   = (const float*)d_in[9];
    const float* bng   = (const float*)d_in[10];
    const float* bnb   = (const float*)d_in[11];
    const float* c2w   = (const float*)d_in[12];
    const float* c2b   = (const float*)d_in[13];
    const float* gw    = (const float*)d_in[14];
    const float* gb    = (const float*)d_in[15];
    const float* clw1  = (const float*)d_in[16];
    const float* clb1  = (const float*)d_in[17];
    const float* clw2  = (const float*)d_in[18];
    const float* clb2  = (const float*)d_in[19];
    float* out = (float*)d_out;

    if (g_s1 == nullptr) {
        cudaStreamCreateWithFlags(&g_s1, cudaStreamNonBlocking);
        for (int i = 0; i < 2; i++) {
            cudaEventCreateWithFlags(&g_eF[i], cudaEventDisableTiming);
            cudaEventCreateWithFlags(&g_eC[i], cudaEventDisableTiming);
        }
    }

    k_embed<<<BB * NSEQ, 64>>>(ids, emb);
    k_entpool<<<BB, 256>>>(e1, e2);
    k_entproj<<<BB, 256>>>(ep_w, ep_b);

    for (int i = 0; i < 2; i++) {
        // fork: conv branch depends only on g_x (complete after entproj / previous gate)
        cudaEventRecord(g_eF[i], 0);
        cudaStreamWaitEvent(g_s1, g_eF[i], 0);
        k_conv<<<dim3(8, 8, BB), 256, 0, g_s1>>>(c1w + i * 288, c1b + i * 32,
                                                 bng + i * 32, bnb + i * 32,
                                                 c2w + i * 288, c2b + i);
        cudaEventRecord(g_eC[i], g_s1);

        // main chain
        if (i == 0) k_presplit<<<BB * NSEQ / 8, 256>>>();
        k_wquant<<<256 * DD / 256, 256>>>(gcn_w + (size_t)i * DD * DD);
        k_sim_mma<<<dim3(4, 2, BB), 256>>>();
        k_topk<<<BB * NSEQ / 128, 128>>>();
        k_inzero<<<BB * NSEQ / 256, 256>>>();
        k_inbuild<<<BB * NSEQ * KTOP / 256, 256>>>();
        k_xqw_mma<<<dim3(8, 256), 256>>>();
        k_gcn_sparse<<<dim3(NSEQ, BB), 128>>>(gcn_b + i * DD);

        // join conv, then gate (emits next layer's splits/norms when i==0)
        cudaStreamWaitEvent(0, g_eC[i], 0);
        k_gate<<<BB * NSEQ, 256>>>(gw, gb, i == 0 ? 1 : 0);
    }
    k_cls<<<BB, 512>>>(clw1, clb1, clw2, clb2, out);
}

// round 8
// speedup vs baseline: 1.1565x; 1.1448x over previous
#include <cuda_runtime.h>
#include <cuda_bf16.h>
#include <math.h>

#define BB    128
#define NSEQ  256
#define DD    512          // NODE
#define DEMB_ 256
#define KTOP  8
#define LABELS_ 19

// ---------------- scratch (device globals; no allocations) ----------------
__device__ float    g_x[BB * NSEQ * DD];       // node features [B,N,512]
__device__ float    g_xn[BB * NSEQ * DD];      // y = x@qw
__device__ float    g_adj[BB * NSEQ * NSEQ];   // sim
__device__ float    g_comb[BB * NSEQ * DD];    // gcn_out
__device__ float    g_conv[BB * NSEQ * DD];    // conv branch output
__device__ float    g_entcat[BB * 2 * DEMB_];
__device__ float    g_rnorm[BB * NSEQ];
__device__ float    g_vals[BB * NSEQ * KTOP];
__device__ int      g_idx[BB * NSEQ * KTOP];
__device__ unsigned g_xh[BB * NSEQ * 256];     // bf16x2 hi, k-pairs packed
__device__ unsigned g_xl[BB * NSEQ * 256];     // bf16x2 lo
__device__ unsigned g_wq[256 * DD];            // quantized W k-pairs
__device__ int      g_incnt[BB * NSEQ];
__device__ int      g_inm[BB * NSEQ * 256];
__device__ float    g_inv[BB * NSEQ * 256];

// ---------------- bf16 helpers ----------------
__device__ __forceinline__ unsigned pack2(float a, float b) {
    __nv_bfloat162 v = __floats2bfloat162_rn(a, b);
    return *(unsigned*)&v;
}
__device__ __forceinline__ void split2(float x, float& h, float& l) {
    __nv_bfloat16 hb = __float2bfloat16_rn(x);
    h = __bfloat162float(hb);
    l = x - h;
}
__device__ __forceinline__ void mma_bf16(float* d, const unsigned* a, const unsigned* b) {
    asm volatile(
        "mma.sync.aligned.m16n8k16.row.col.f32.bf16.bf16.f32 "
        "{%0,%1,%2,%3}, {%4,%5,%6,%7}, {%8,%9}, {%0,%1,%2,%3};"
        : "+f"(d[0]), "+f"(d[1]), "+f"(d[2]), "+f"(d[3])
        : "r"(a[0]), "r"(a[1]), "r"(a[2]), "r"(a[3]), "r"(b[0]), "r"(b[1]));
}

// ---------------- embedding gather ----------------
__global__ void k_embed(const int* __restrict__ ids, const float* __restrict__ emb) {
    int row = blockIdx.x;
    int id = ids[row];
    const float4* src = (const float4*)(emb + (size_t)id * DEMB_);
    float4* dst = (float4*)(g_x + (size_t)row * DD);
    dst[threadIdx.x] = src[threadIdx.x];
}

// ---------------- entity masked-mean pooling ----------------
__global__ void k_entpool(const float* __restrict__ e1, const float* __restrict__ e2) {
    int b = blockIdx.x;
    int t = threadIdx.x;
    __shared__ float m1[NSEQ], m2[NSEQ];
    __shared__ float c1s, c2s;
    m1[t] = e1[b * NSEQ + t];
    m2[t] = e2[b * NSEQ + t];
    __syncthreads();
    if (t == 0) {
        float a = 0.f, c = 0.f;
        for (int n = 0; n < NSEQ; n++) { a += m1[n]; c += m2[n]; }
        c1s = a; c2s = c;
    }
    __syncthreads();
    float s1 = 0.f, s2 = 0.f;
    const float* xb = g_x + (size_t)b * NSEQ * DD;
    for (int n = 0; n < NSEQ; n++) {
        float v = xb[(size_t)n * DD + t];
        s1 += v * m1[n];
        s2 += v * m2[n];
    }
    g_entcat[b * 512 + t]       = s1 / (c1s + 1e-13f);
    g_entcat[b * 512 + 256 + t] = s2 / (c2s + 1e-13f);
}

// ---------------- ent = entcat @ ep_w + ep_b, broadcast ----------------
__global__ void k_entproj(const float* __restrict__ ep_w, const float* __restrict__ ep_b) {
    int b = blockIdx.x;
    int j = threadIdx.x;
    __shared__ float ec[512];
    __shared__ float accs[256];
    ec[j]       = g_entcat[b * 512 + j];
    ec[j + 256] = g_entcat[b * 512 + j + 256];
    __syncthreads();
    float acc = ep_b[j];
    for (int d = 0; d < 512; d++) acc += ec[d] * ep_w[d * DEMB_ + j];
    accs[j] = acc;
    __syncthreads();
    float* xb = g_x + (size_t)b * NSEQ * DD;
    for (int i = j; i < NSEQ * 256; i += 256) {
        int n = i >> 8, c = i & 255;
        xb[(size_t)n * DD + DEMB_ + c] = accs[c];
    }
}

// ---------------- presplit: x -> bf16x2 hi/lo + inv-norms (layer 0 only) ----------------
__global__ void k_presplit() {
    int row = blockIdx.x * 8 + (threadIdx.x >> 5);
    int lane = threadIdx.x & 31;
    const float4* xr = (const float4*)(g_x + (size_t)row * DD);
    uint2* xh2 = (uint2*)(g_xh + (size_t)row * 256);
    uint2* xl2 = (uint2*)(g_xl + (size_t)row * 256);
    float ss = 0.f;
    #pragma unroll
    for (int q = 0; q < 4; q++) {
        int w = lane + q * 32;
        float4 v = xr[w];
        ss += v.x * v.x + v.y * v.y + v.z * v.z + v.w * v.w;
        float hx, lx, hy, ly, hz, lz, hw, lw;
        split2(v.x, hx, lx); split2(v.y, hy, ly);
        split2(v.z, hz, lz); split2(v.w, hw, lw);
        uint2 H; H.x = pack2(hx, hy); H.y = pack2(hz, hw);
        uint2 L; L.x = pack2(lx, ly); L.y = pack2(lz, lw);
        xh2[w] = H;
        xl2[w] = L;
    }
    #pragma unroll
    for (int o = 16; o > 0; o >>= 1) ss += __shfl_xor_sync(0xffffffffu, ss, o);
    if (lane == 0) g_rnorm[row] = 1.f / fmaxf(sqrtf(ss), 1e-12f);
}

// ---------------- quantize W into packed bf16x2 k-pairs ----------------
__global__ void k_wquant(const float* __restrict__ W) {
    int t = blockIdx.x * 256 + threadIdx.x;
    int kp = t >> 9, n = t & 511;
    float w0 = W[(size_t)(2 * kp) * DD + n];
    float w1 = W[(size_t)(2 * kp + 1) * DD + n];
    float q0 = (w0 > 0.1f) ? 1.f : ((w0 < -0.1f) ? -1.f : 0.f);
    float q1 = (w1 > 0.1f) ? 1.f : ((w1 < -0.1f) ? -1.f : 0.f);
    g_wq[t] = pack2(q0, q1);
}

// ---------------- sim = (x @ x^T) * rn_i * rn_j via 2-split bf16 MMA ----------------
__global__ __launch_bounds__(256) void k_sim_mma() {
    int b = blockIdx.z;
    int i0 = blockIdx.y * 128, j0 = blockIdx.x * 64;
    size_t bN = (size_t)b * NSEQ;
    __shared__ unsigned Ah[8][136], Al[8][136];
    __shared__ unsigned Bh[8][72],  Bl[8][72];
    __shared__ float rnI[128], rnJ[64];
    int t = threadIdx.x;
    int lane = t & 31, wid = t >> 5;
    int wm = wid >> 1, wn = wid & 1;
    int g = lane >> 2, tig = lane & 3;
    if (t < 128) rnI[t] = g_rnorm[bN + i0 + t];
    else if (t < 192) rnJ[t - 128] = g_rnorm[bN + j0 + t - 128];
    float acc[2][4][4];
    #pragma unroll
    for (int a = 0; a < 2; a++)
        #pragma unroll
        for (int n = 0; n < 4; n++)
            #pragma unroll
            for (int e = 0; e < 4; e++) acc[a][n][e] = 0.f;

    int arow = t >> 1, aseg = t & 1;
    for (int kw = 0; kw < 256; kw += 8) {
        {
            uint4 h = *(const uint4*)(g_xh + (bN + i0 + arow) * 256 + kw + aseg * 4);
            uint4 l = *(const uint4*)(g_xl + (bN + i0 + arow) * 256 + kw + aseg * 4);
            Ah[aseg * 4 + 0][arow] = h.x; Ah[aseg * 4 + 1][arow] = h.y;
            Ah[aseg * 4 + 2][arow] = h.z; Ah[aseg * 4 + 3][arow] = h.w;
            Al[aseg * 4 + 0][arow] = l.x; Al[aseg * 4 + 1][arow] = l.y;
            Al[aseg * 4 + 2][arow] = l.z; Al[aseg * 4 + 3][arow] = l.w;
        }
        if (t < 128) {
            int r = t >> 1, s = t & 1;
            uint4 h = *(const uint4*)(g_xh + (bN + j0 + r) * 256 + kw + s * 4);
            Bh[s * 4 + 0][r] = h.x; Bh[s * 4 + 1][r] = h.y;
            Bh[s * 4 + 2][r] = h.z; Bh[s * 4 + 3][r] = h.w;
        } else {
            int tt = t - 128;
            int r = tt >> 1, s = tt & 1;
            uint4 l = *(const uint4*)(g_xl + (bN + j0 + r) * 256 + kw + s * 4);
            Bl[s * 4 + 0][r] = l.x; Bl[s * 4 + 1][r] = l.y;
            Bl[s * 4 + 2][r] = l.z; Bl[s * 4 + 3][r] = l.w;
        }
        __syncthreads();
        unsigned ah[2][4], al[2][4], bh[4][2], bl[4][2];
        #pragma unroll
        for (int mt = 0; mt < 2; mt++) {
            int r = wm * 32 + mt * 16 + g;
            ah[mt][0] = Ah[tig][r];     ah[mt][1] = Ah[tig][r + 8];
            ah[mt][2] = Ah[tig + 4][r]; ah[mt][3] = Ah[tig + 4][r + 8];
            al[mt][0] = Al[tig][r];     al[mt][1] = Al[tig][r + 8];
            al[mt][2] = Al[tig + 4][r]; al[mt][3] = Al[tig + 4][r + 8];
        }
        #pragma unroll
        for (int nt = 0; nt < 4; nt++) {
            int n = wn * 32 + nt * 8 + g;
            bh[nt][0] = Bh[tig][n]; bh[nt][1] = Bh[tig + 4][n];
            bl[nt][0] = Bl[tig][n]; bl[nt][1] = Bl[tig + 4][n];
        }
        #pragma unroll
        for (int mt = 0; mt < 2; mt++)
            #pragma unroll
            for (int nt = 0; nt < 4; nt++) {
                mma_bf16(acc[mt][nt], ah[mt], bh[nt]);
                mma_bf16(acc[mt][nt], ah[mt], bl[nt]);
                mma_bf16(acc[mt][nt], al[mt], bh[nt]);
            }
        __syncthreads();
    }
    float* C = g_adj + (size_t)b * NSEQ * NSEQ;
    #pragma unroll
    for (int mt = 0; mt < 2; mt++)
        #pragma unroll
        for (int nt = 0; nt < 4; nt++) {
            int rl = wm * 32 + mt * 16 + g;
            int cl = wn * 32 + nt * 8 + tig * 2;
            int r = i0 + rl, c = j0 + cl;
            float s0 = rnI[rl] * rnJ[cl], s1 = rnI[rl] * rnJ[cl + 1];
            float s2 = rnI[rl + 8] * rnJ[cl], s3 = rnI[rl + 8] * rnJ[cl + 1];
            C[(size_t)r * NSEQ + c]           = acc[mt][nt][0] * s0;
            C[(size_t)r * NSEQ + c + 1]       = acc[mt][nt][1] * s1;
            C[(size_t)(r + 8) * NSEQ + c]     = acc[mt][nt][2] * s2;
            C[(size_t)(r + 8) * NSEQ + c + 1] = acc[mt][nt][3] * s3;
        }
}

// ---------------- top-8 with coalesced smem staging (+ zero incnt) ----------------
__global__ __launch_bounds__(128) void k_topk() {
    __shared__ float sh[128][36];
    int rb = blockIdx.x * 128;
    int t = threadIdx.x;
    float v[KTOP]; int id[KTOP];
    #pragma unroll
    for (int k = 0; k < KTOP; k++) { v[k] = -1e30f; id[k] = -1; }
    for (int ch = 0; ch < 8; ch++) {
        __syncthreads();
        for (int q = t; q < 1024; q += 128) {
            int row = q >> 3, c4 = q & 7;
            float4 x = *(const float4*)(g_adj + (size_t)(rb + row) * NSEQ + ch * 32 + c4 * 4);
            *(float4*)&sh[row][c4 * 4] = x;
        }
        __syncthreads();
        #pragma unroll 4
        for (int c = 0; c < 32; c++) {
            float x = sh[t][c];
            if (x > v[KTOP - 1]) {
                int m = ch * 32 + c;
                int p = KTOP - 1;
                while (p > 0 && v[p - 1] < x) { v[p] = v[p - 1]; id[p] = id[p - 1]; p--; }
                v[p] = x; id[p] = m;
            }
        }
    }
    int row = rb + t;
    g_incnt[row] = 0;
    #pragma unroll
    for (int k = 0; k < KTOP; k++) {
        g_vals[row * KTOP + k] = v[k];
        g_idx[row * KTOP + k]  = id[k];
    }
}

// ---------------- build incoming adjacency lists ----------------
__global__ void k_inbuild() {
    int t = blockIdx.x * blockDim.x + threadIdx.x;
    if (t >= BB * NSEQ * KTOP) return;
    int row = t >> 3;
    int b = row >> 8;
    int n = row & 255;
    int j = g_idx[t];
    float v = g_vals[t];
    int node = b * 256 + j;
    int pos = atomicAdd(&g_incnt[node], 1);
    g_inm[((size_t)node << 8) + pos] = n;
    g_inv[((size_t)node << 8) + pos] = v;
}

// ---------------- xqw = x @ sign(W) * 0.1 via 2-split bf16 MMA ----------------
__global__ __launch_bounds__(256) void k_xqw_mma() {
    int i0 = blockIdx.y * 128, j0 = blockIdx.x * 64;
    __shared__ unsigned Ah[8][136], Al[8][136];
    __shared__ unsigned Bq[8][72];
    int t = threadIdx.x;
    int lane = t & 31, wid = t >> 5;
    int wm = wid >> 1, wn = wid & 1;
    int g = lane >> 2, tig = lane & 3;
    float acc[2][4][4];
    #pragma unroll
    for (int a = 0; a < 2; a++)
        #pragma unroll
        for (int n = 0; n < 4; n++)
            #pragma unroll
            for (int e = 0; e < 4; e++) acc[a][n][e] = 0.f;

    int arow = t >> 1, aseg = t & 1;
    int bkp = t >> 5, bn = (t & 31) * 2;
    for (int kw = 0; kw < 256; kw += 8) {
        {
            uint4 h = *(const uint4*)(g_xh + (size_t)(i0 + arow) * 256 + kw + aseg * 4);
            uint4 l = *(const uint4*)(g_xl + (size_t)(i0 + arow) * 256 + kw + aseg * 4);
            Ah[aseg * 4 + 0][arow] = h.x; Ah[aseg * 4 + 1][arow] = h.y;
            Ah[aseg * 4 + 2][arow] = h.z; Ah[aseg * 4 + 3][arow] = h.w;
            Al[aseg * 4 + 0][arow] = l.x; Al[aseg * 4 + 1][arow] = l.y;
            Al[aseg * 4 + 2][arow] = l.z; Al[aseg * 4 + 3][arow] = l.w;
        }
        {
            uint2 w = *(const uint2*)(g_wq + (size_t)(kw + bkp) * DD + j0 + bn);
            Bq[bkp][bn] = w.x; Bq[bkp][bn + 1] = w.y;
        }
        __syncthreads();
        unsigned ah[2][4], al[2][4], bq[4][2];
        #pragma unroll
        for (int mt = 0; mt < 2; mt++) {
            int r = wm * 32 + mt * 16 + g;
            ah[mt][0] = Ah[tig][r];     ah[mt][1] = Ah[tig][r + 8];
            ah[mt][2] = Ah[tig + 4][r]; ah[mt][3] = Ah[tig + 4][r + 8];
            al[mt][0] = Al[tig][r];     al[mt][1] = Al[tig][r + 8];
            al[mt][2] = Al[tig + 4][r]; al[mt][3] = Al[tig + 4][r + 8];
        }
        #pragma unroll
        for (int nt = 0; nt < 4; nt++) {
            int n = wn * 32 + nt * 8 + g;
            bq[nt][0] = Bq[tig][n]; bq[nt][1] = Bq[tig + 4][n];
        }
        #pragma unroll
        for (int mt = 0; mt < 2; mt++)
            #pragma unroll
            for (int nt = 0; nt < 4; nt++) {
                mma_bf16(acc[mt][nt], ah[mt], bq[nt]);
                mma_bf16(acc[mt][nt], al[mt], bq[nt]);
            }
        __syncthreads();
    }
    #pragma unroll
    for (int mt = 0; mt < 2; mt++)
        #pragma unroll
        for (int nt = 0; nt < 4; nt++) {
            int r = i0 + wm * 32 + mt * 16 + g;
            int c = j0 + wn * 32 + nt * 8 + tig * 2;
            g_xn[(size_t)r * DD + c]           = 0.1f * acc[mt][nt][0];
            g_xn[(size_t)r * DD + c + 1]       = 0.1f * acc[mt][nt][1];
            g_xn[(size_t)(r + 8) * DD + c]     = 0.1f * acc[mt][nt][2];
            g_xn[(size_t)(r + 8) * DD + c + 1] = 0.1f * acc[mt][nt][3];
        }
}

// ---------------- sparse GCN ----------------
__global__ __launch_bounds__(128) void k_gcn_sparse(const float* __restrict__ bias) {
    int b = blockIdx.y, n = blockIdx.x;
    int node = b * 256 + n;
    int t = threadIdx.x;
    __shared__ int   s_src[264];
    __shared__ float s_val[264];
    __shared__ int   s_cnt;
    if (t == 0) s_cnt = g_incnt[node];
    if (t < 8) {
        s_src[t] = g_idx[node * KTOP + t];
        s_val[t] = g_vals[node * KTOP + t];
    }
    __syncthreads();
    int cnt = s_cnt;
    for (int i = t; i < cnt; i += 128) {
        s_src[8 + i] = g_inm[((size_t)node << 8) + i];
        s_val[8 + i] = g_inv[((size_t)node << 8) + i];
    }
    __syncthreads();
    int tot = 8 + cnt;
    const float* Yb = g_xn + (size_t)b * NSEQ * DD;
    float a0 = 0.f, a1 = 0.f, a2 = 0.f, a3 = 0.f;
    for (int e = 0; e < tot; e++) {
        float v = 0.5f * s_val[e];
        const float* yr = Yb + (size_t)s_src[e] * DD;
        a0 += v * yr[t];
        a1 += v * yr[t + 128];
        a2 += v * yr[t + 256];
        a3 += v * yr[t + 384];
    }
    float* C = g_comb + (size_t)node * DD;
    C[t]       = fmaxf(a0 + bias[t], 0.f);
    C[t + 128] = fmaxf(a1 + bias[t + 128], 0.f);
    C[t + 256] = fmaxf(a2 + bias[t + 256], 0.f);
    C[t + 384] = fmaxf(a3 + bias[t + 384], 0.f);
}

// ---------------- fused conv v3: vectorized, hoisted, conflict-free ----------------
// tile 32x64 out; xt rows 36 (oy0-2..+33), cols 68 (+pad 72)
// hs[cl] rows: hr = global oy0-1+hr (hr<34 valid); cols: hc = global ox0-1+hc (hc<66 valid)
__global__ __launch_bounds__(256) void k_conv(const float* __restrict__ c1w, const float* __restrict__ c1b,
                                              const float* __restrict__ bng, const float* __restrict__ bnb,
                                              const float* __restrict__ c2w, const float* __restrict__ c2b) {
    __shared__ float xt[36][72];
    __shared__ float hs[2][36][72];
    __shared__ float w1s[32][9], w2s[32][9], scs[32], tcs[32];
    int b = blockIdx.z;
    int oy0 = blockIdx.y * 32, ox0 = blockIdx.x * 64;
    int t = threadIdx.x;
    if (t < 32) {
        float s = bng[t] * rsqrtf(1.f + 1e-5f);
        scs[t] = s;
        tcs[t] = c1b[t] * s + bnb[t];
    }
    for (int i = t; i < 288; i += 256) {
        w1s[i / 9][i % 9] = c1w[i];
        w2s[i / 9][i % 9] = c2w[i];
    }
    const float* xb = g_x + (size_t)b * NSEQ * DD;
    for (int i = t; i < 36 * 72; i += 256) {
        int r = i / 72, c = i % 72;
        int gy = oy0 - 2 + r, gx = ox0 - 2 + c;
        xt[r][c] = (c < 68 && gy >= 0 && gy < NSEQ && gx >= 0 && gx < DD) ? xb[(size_t)gy * DD + gx] : 0.f;
    }
    __syncthreads();

    // ---- hoisted stage-1 task decode (tasks: cl(2) x rg(9) x cg(17) = 306) ----
    int taskN = (t < 50) ? 2 : 1;
    int tcl[2], thr0[2], thc0[2];
    float rmask[2][4], cmask[2][4];
    #pragma unroll
    for (int q = 0; q < 2; q++) {
        int tau = t + q * 256;
        if (tau >= 306) tau = 0;          // dummy (only used when q < taskN)
        int cl = tau / 153;
        int r9 = tau - cl * 153;
        int rg = r9 / 17, cg = r9 - rg * 17;
        tcl[q] = cl; thr0[q] = rg * 4; thc0[q] = cg * 4;
        #pragma unroll
        for (int i = 0; i < 4; i++) {
            int hr = rg * 4 + i, gy = oy0 - 1 + hr;
            rmask[q][i] = (hr < 34 && gy >= 0 && gy < NSEQ) ? 1.f : 0.f;
        }
        #pragma unroll
        for (int j = 0; j < 4; j++) {
            int hc = cg * 4 + j, gx = ox0 - 1 + hc;
            cmask[q][j] = (hc < 66 && gx >= 0 && gx < DD) ? 1.f : 0.f;
        }
    }

    // ---- hoisted stage-2 mapping: lane-fast columns ----
    int kx = t & 31, rg2 = t >> 5;
    int ox = kx * 2, oy = rg2 * 4;
    float acc2[4][2] = {};

    for (int chunk = 0; chunk < 16; chunk++) {
        // ---- stage 1: h for 2 channels, 4x4 tiles, row-streaming ----
        for (int q = 0; q < taskN; q++) {
            int cg2 = chunk * 2 + tcl[q];
            int hr0 = thr0[q], hc0 = thc0[q];
            float w[9];
            #pragma unroll
            for (int u = 0; u < 9; u++) w[u] = w1s[cg2][u];
            float sc = scs[cg2], tc = tcs[cg2];
            float a1[4][4] = {};
            #pragma unroll
            for (int r = 0; r < 6; r++) {
                int rr = hr0 + r; if (rr > 35) rr = 35;
                float4 pa = *(const float4*)&xt[rr][hc0];
                float4 pb = *(const float4*)&xt[rr][hc0 + 4];
                float row[8] = {pa.x, pa.y, pa.z, pa.w, pb.x, pb.y, pb.z, pb.w};
                #pragma unroll
                for (int i = 0; i < 4; i++) {
                    if (r >= i && r <= i + 2) {
                        int dy = r - i;
                        #pragma unroll
                        for (int j = 0; j < 4; j++)
                            a1[i][j] += row[j] * w[dy * 3] + row[j + 1] * w[dy * 3 + 1]
                                      + row[j + 2] * w[dy * 3 + 2];
                    }
                }
            }
            #pragma unroll
            for (int i = 0; i < 4; i++) {
                float4 st;
                float* stf = (float*)&st;
                #pragma unroll
                for (int j = 0; j < 4; j++) {
                    float hv = fmaxf(a1[i][j] * sc + tc, 0.f);
                    stf[j] = hv * rmask[q][i] * cmask[q][j];
                }
                *(float4*)&hs[tcl[q]][hr0 + i][hc0] = st;
            }
        }
        __syncthreads();
        // ---- stage 2: accumulate conv2 for 2 channels ----
        #pragma unroll
        for (int cl = 0; cl < 2; cl++) {
            int cg2 = chunk * 2 + cl;
            float w[9];
            #pragma unroll
            for (int u = 0; u < 9; u++) w[u] = w2s[cg2][u];
            float hb[6][4];
            #pragma unroll
            for (int r = 0; r < 6; r++) {
                float2 u0 = *(const float2*)&hs[cl][oy + r][ox];
                float2 u1 = *(const float2*)&hs[cl][oy + r][ox + 2];
                hb[r][0] = u0.x; hb[r][1] = u0.y; hb[r][2] = u1.x; hb[r][3] = u1.y;
            }
            #pragma unroll
            for (int i = 0; i < 4; i++)
                #pragma unroll
                for (int j = 0; j < 2; j++)
                    #pragma unroll
                    for (int dy = 0; dy < 3; dy++)
                        #pragma unroll
                        for (int dx = 0; dx < 3; dx++)
                            acc2[i][j] += hb[i + dy][j + dx] * w[dy * 3 + dx];
        }
        __syncthreads();
    }
    float bias = c2b[0];
    #pragma unroll
    for (int i = 0; i < 4; i++)
        #pragma unroll
        for (int j = 0; j < 2; j++)
            hs[0][oy + i][ox + j] = acc2[i][j] + bias;
    __syncthreads();
    float* cb = g_conv + (size_t)b * NSEQ * DD;
    for (int i = t; i < 32 * 64; i += 256) {
        int r = i >> 6, c = i & 63;
        cb[(size_t)(oy0 + r) * DD + ox0 + c] = hs[0][r][c];
    }
}

// ---------------- gate + residual mix (+ optional split/norm emit) ----------------
__global__ void k_gate(const float* __restrict__ gw, const float* __restrict__ gb, int emit) {
    int row = blockIdx.x;
    int t = threadIdx.x;
    size_t off = (size_t)row * DD;
    __shared__ float ws[8], ws2[8];
    __shared__ float xr[512];
    float x1 = g_x[off + t],    x2 = g_x[off + t + 256];
    float c1 = g_comb[off + t] + g_conv[off + t];
    float c2 = g_comb[off + t + 256] + g_conv[off + t + 256];
    float p = x1 * gw[t] + x2 * gw[t + 256] + c1 * gw[512 + t] + c2 * gw[768 + t];
    #pragma unroll
    for (int o = 16; o > 0; o >>= 1) p += __shfl_xor_sync(0xffffffffu, p, o);
    if ((t & 31) == 0) ws[t >> 5] = p;
    __syncthreads();
    float tot = ws[0] + ws[1] + ws[2] + ws[3] + ws[4] + ws[5] + ws[6] + ws[7];
    float g = 1.f / (1.f + expf(-(tot + gb[0])));
    float y1 = g * x1 + (1.f - g) * c1;
    float y2 = g * x2 + (1.f - g) * c2;
    g_x[off + t]       = y1;
    g_x[off + t + 256] = y2;
    if (emit) {
        xr[t] = y1; xr[t + 256] = y2;
        float ssp = y1 * y1 + y2 * y2;
        #pragma unroll
        for (int o = 16; o > 0; o >>= 1) ssp += __shfl_xor_sync(0xffffffffu, ssp, o);
        if ((t & 31) == 0) ws2[t >> 5] = ssp;
        __syncthreads();
        if (t == 0) {
            float ss = ws2[0] + ws2[1] + ws2[2] + ws2[3] + ws2[4] + ws2[5] + ws2[6] + ws2[7];
            g_rnorm[row] = 1.f / fmaxf(sqrtf(ss), 1e-12f);
        }
        float a = xr[2 * t], bb = xr[2 * t + 1];
        float ha, la, hb2, lb2;
        split2(a, ha, la);
        split2(bb, hb2, lb2);
        g_xh[(size_t)row * 256 + t] = pack2(ha, hb2);
        g_xl[(size_t)row * 256 + t] = pack2(la, lb2);
    }
}

// ---------------- mean pool + classifier ----------------
__global__ void k_cls(const float* __restrict__ w1, const float* __restrict__ b1,
                      const float* __restrict__ w2, const float* __restrict__ b2,
                      float* __restrict__ out) {
    int b = blockIdx.x;
    int t = threadIdx.x;
    __shared__ float pooled[512], h1[512];
    float s = 0.f;
    const float* xb = g_x + (size_t)b * NSEQ * DD;
    for (int n = 0; n < NSEQ; n++) s += xb[(size_t)n * DD + t];
    pooled[t] = s * (1.f / NSEQ);
    __syncthreads();
    float a = b1[t];
    for (int d = 0; d < 512; d++) a += pooled[d] * w1[d * 512 + t];
    h1[t] = fmaxf(a, 0.f);
    __syncthreads();
    if (t < LABELS_) {
        float a2 = b2[t];
        for (int d = 0; d < 512; d++) a2 += h1[d] * w2[d * LABELS_ + t];
        out[b * LABELS_ + t] = a2;
    }
}

// ---------------- launch ----------------
static cudaStream_t g_s1 = nullptr;
static cudaEvent_t  g_eF[2], g_eC[2];

extern "C" void kernel_launch(void* const* d_in, const int* in_sizes, int n_in,
                              void* d_out, int out_size) {
    const int*   ids   = (const int*)  d_in[0];
    const float* e1    = (const float*)d_in[1];
    const float* e2    = (const float*)d_in[2];
    const float* emb   = (const float*)d_in[3];
    const float* ep_w  = (const float*)d_in[4];
    const float* ep_b  = (const float*)d_in[5];
    const float* gcn_w = (const float*)d_in[6];
    const float* gcn_b = (const float*)d_in[7];
    const float* c1w   = (const float*)d_in[8];
    const float* c1b   = (const float*)d_in[9];
    const float* bng   = (const float*)d_in[10];
    const float* bnb   = (const float*)d_in[11];
    const float* c2w   = (const float*)d_in[12];
    const float* c2b   = (const float*)d_in[13];
    const float* gw    = (const float*)d_in[14];
    const float* gb    = (const float*)d_in[15];
    const float* clw1  = (const float*)d_in[16];
    const float* clb1  = (const float*)d_in[17];
    const float* clw2  = (const float*)d_in[18];
    const float* clb2  = (const float*)d_in[19];
    float* out = (float*)d_out;

    if (g_s1 == nullptr) {
        cudaStreamCreateWithFlags(&g_s1, cudaStreamNonBlocking);
        for (int i = 0; i < 2; i++) {
            cudaEventCreateWithFlags(&g_eF[i], cudaEventDisableTiming);
            cudaEventCreateWithFlags(&g_eC[i], cudaEventDisableTiming);
        }
    }

    k_embed<<<BB * NSEQ, 64>>>(ids, emb);
    k_entpool<<<BB, 256>>>(e1, e2);
    k_entproj<<<BB, 256>>>(ep_w, ep_b);

    for (int i = 0; i < 2; i++) {
        cudaEventRecord(g_eF[i], 0);
        cudaStreamWaitEvent(g_s1, g_eF[i], 0);
        k_conv<<<dim3(8, 8, BB), 256, 0, g_s1>>>(c1w + i * 288, c1b + i * 32,
                                                 bng + i * 32, bnb + i * 32,
                                                 c2w + i * 288, c2b + i);
        cudaEventRecord(g_eC[i], g_s1);

        if (i == 0) k_presplit<<<BB * NSEQ / 8, 256>>>();
        k_wquant<<<256 * DD / 256, 256>>>(gcn_w + (size_t)i * DD * DD);
        k_sim_mma<<<dim3(4, 2, BB), 256>>>();
        k_topk<<<BB * NSEQ / 128, 128>>>();
        k_inbuild<<<BB * NSEQ * KTOP / 256, 256>>>();
        k_xqw_mma<<<dim3(8, 256), 256>>>();
        k_gcn_sparse<<<dim3(NSEQ, BB), 128>>>(gcn_b + i * DD);

        cudaStreamWaitEvent(0, g_eC[i], 0);
        k_gate<<<BB * NSEQ, 256>>>(gw, gb, i == 0 ? 1 : 0);
    }
    k_cls<<<BB, 512>>>(clw1, clb1, clw2, clb2, out);
}